// round 3
// baseline (speedup 1.0000x reference)
#include <cuda_runtime.h>

// B3-spline à-trous UWT, J=3, fused single kernel.
// (8,1024,1024) fp32 -> (8,4,1024,1024) fp32 = [w1,w2,w3,c3]
//
// One block = 64x64 output tile, halo 14 -> 92x92 region, reflect-indexed load.
// TWO smem buffers (A,B), 73.6KB -> 3 CTAs/SM (24 warps).
// Pipeline: load->A; then per level: hconv A->B (vertical), wconv B->A
// (horizontal) FUSED with the wavelet diff: each output thread reads the old
// coefficient a=A[loc] (it is the sole owner of loc -> no race), writes the
// new coefficient c, and stores w = a-c (and c3 at the last level) to gmem.
// All smem access is float4, pitch 100 (%32==4 -> conflict-free both ways).

namespace {

constexpr int TS    = 64;
constexpr int HALO  = 14;            // 2*(1+2+4)
constexpr int IN    = TS + 2 * HALO; // 92
constexpr int PITCH = 100;           // floats; %32==4
constexpr int COFF  = 2;             // data at float cols [2,94)
constexpr int NT    = 256;
constexpr int IMG_H = 1024, IMG_W = 1024;
constexpr int SMEM_ELEMS = IN * PITCH;          // 9200
constexpr int SMEM_BYTES = 2 * SMEM_ELEMS * 4;  // 73600 -> 3 CTAs/SM

constexpr float B3W0 = 0.0625f;
constexpr float B3W1 = 0.25f;
constexpr float B3W2 = 0.375f;

__device__ __forceinline__ float4 ld4(const float* p) {
    return *reinterpret_cast<const float4*>(p);
}
__device__ __forceinline__ void st4(float* p, float4 v) {
    *reinterpret_cast<float4*>(p) = v;
}
__device__ __forceinline__ float b3s(float a, float b, float c, float d, float e) {
    return fmaf(c, B3W2, fmaf(b + d, B3W1, (a + e) * B3W0));
}
__device__ __forceinline__ float4 b3v(float4 a, float4 b, float4 c, float4 d, float4 e) {
    float4 r;
    r.x = b3s(a.x, b.x, c.x, d.x, e.x);
    r.y = b3s(a.y, b.y, c.y, d.y, e.y);
    r.z = b3s(a.z, b.z, c.z, d.z, e.z);
    r.w = b3s(a.w, b.w, c.w, d.w, e.w);
    return r;
}

// Vertical 5-tap conv, dilation D: rows [R0,R1) in NSEGR segments,
// vec cols [VC0,VC1). Per unit: D phase streams, 5-deep float4 window.
template <int D, int R0, int R1, int NSEGR, int VC0, int VC1>
__device__ __forceinline__ void hconv_v(const float* __restrict__ src,
                                        float* __restrict__ dst, int tid) {
    constexpr int NCV = VC1 - VC0;
    constexpr int NR  = R1 - R0;
    constexpr int SEG = NR / NSEGR;
    constexpr int NIT = SEG / D;
    constexpr int UNITS = NCV * NSEGR;
    static_assert(SEG * NSEGR == NR && NIT * D == SEG, "divisibility");
    for (int u = tid; u < UNITS; u += NT) {
        const int vc = VC0 + u % NCV;
        const int rs = R0 + (u / NCV) * SEG;
        const float* s = src + 4 * vc;
        float* d = dst + 4 * vc;
#pragma unroll
        for (int p = 0; p < D; ++p) {
            int r = rs + p;
            float4 v0 = ld4(s + (r - 2 * D) * PITCH);
            float4 v1 = ld4(s + (r - D) * PITCH);
            float4 v2 = ld4(s + r * PITCH);
            float4 v3 = ld4(s + (r + D) * PITCH);
#pragma unroll
            for (int i = 0; i < NIT; ++i, r += D) {
                const float4 v4 = ld4(s + (r + 2 * D) * PITCH);
                st4(d + r * PITCH, b3v(v0, v1, v2, v3, v4));
                v0 = v1; v1 = v2; v2 = v3; v3 = v4;
            }
        }
    }
}

// Horizontal 5-tap conv, dilation D, FUSED with wavelet diff + gmem store.
// Reads smoothed rows from src; for each output loc: c = conv, a = dst[loc]
// (old coefficient; this thread is sole reader+writer of loc), dst[loc] = c,
// and for center locs stores w = a - c (and c when C3) to gmem.
template <int D, int R0, int R1, int VC0, int VC1, int NSEGC, bool C3>
__device__ __forceinline__ void wconv_fused(const float* __restrict__ src,
                                            float* __restrict__ dst,
                                            float* __restrict__ wout,
                                            float* __restrict__ c3out,
                                            int tid) {
    constexpr int NR   = R1 - R0;
    constexpr int NCV  = VC1 - VC0;
    constexpr int SEGV = NCV / NSEGC;
    constexpr int UNITS = NR * NSEGC;
    constexpr int BL = (D == 4) ? 2 : 1;
    constexpr int TH = (D == 4) ? 2 : 1;
    constexpr int NV = BL + 1 + TH;
    static_assert(SEGV * NSEGC == NCV, "divisibility");
    for (int u = tid; u < UNITS; u += NT) {
        const int r   = R0 + u % NR;
        const int vcs = VC0 + (u / NR) * SEGV;
        const float* s = src + r * PITCH;
        float* d = dst + r * PITCH;
        const bool rcen = (r >= HALO) && (r < HALO + TS);
        float w[4 * NV];
#pragma unroll
        for (int k = 0; k < NV; ++k) {
            const float4 t = ld4(s + 4 * (vcs - BL + k));
            w[4 * k + 0] = t.x; w[4 * k + 1] = t.y;
            w[4 * k + 2] = t.z; w[4 * k + 3] = t.w;
        }
#pragma unroll
        for (int i = 0; i < SEGV; ++i) {
            const int vc = vcs + i;
            constexpr int C = 4 * BL;
            float4 o;
            o.x = b3s(w[C - 2 * D],     w[C - D],     w[C],     w[C + D],     w[C + 2 * D]);
            o.y = b3s(w[C + 1 - 2 * D], w[C + 1 - D], w[C + 1], w[C + 1 + D], w[C + 1 + 2 * D]);
            o.z = b3s(w[C + 2 - 2 * D], w[C + 2 - D], w[C + 2], w[C + 2 + D], w[C + 2 + 2 * D]);
            o.w = b3s(w[C + 3 - 2 * D], w[C + 3 - D], w[C + 3], w[C + 3 + D], w[C + 3 + 2 * D]);
            if (rcen && vc >= 4 && vc < 20) {
                const float4 a = ld4(d + 4 * vc);   // old coefficient
                const size_t go = (size_t)(r - HALO) * IMG_W + (4 * vc - 16);
                st4(wout + go, make_float4(a.x - o.x, a.y - o.y,
                                           a.z - o.z, a.w - o.w));
                if (C3) st4(c3out + go, o);
            }
            st4(d + 4 * vc, o);                     // new coefficient
            if (i < SEGV - 1) {
#pragma unroll
                for (int k = 0; k < 4 * (NV - 1); ++k) w[k] = w[k + 4];
                const float4 t = ld4(s + 4 * (vc + 1 + TH));
                w[4 * NV - 4] = t.x; w[4 * NV - 3] = t.y;
                w[4 * NV - 2] = t.z; w[4 * NV - 1] = t.w;
            }
        }
    }
}

}  // namespace

__global__ void __launch_bounds__(NT, 3)
b3_uwt_kernel(const float* __restrict__ x, float* __restrict__ out) {
    extern __shared__ float sm[];
    float* Ab = sm;
    float* Bb = sm + SMEM_ELEMS;

    const int tid = threadIdx.x;
    const int gc0 = blockIdx.x * TS;
    const int gr0 = blockIdx.y * TS;
    const int b   = blockIdx.z;

    const float* xb = x + (size_t)b * IMG_H * IMG_W;

    // ---- load 92x92 region into A (float cols [2,94)) ----
    const bool interior = (gr0 >= HALO) && (gr0 + TS + HALO <= IMG_H) &&
                          (gc0 >= HALO) && (gc0 + TS + HALO <= IMG_W);
    if (interior) {
        constexpr int L2N = IN / 2;  // 46 float2 per row
        const float* base = xb + (size_t)(gr0 - HALO) * IMG_W + (gc0 - HALO);
        for (int u = tid; u < IN * L2N; u += NT) {
            const int r = u / L2N;
            const int k = u - r * L2N;
            const float2 v =
                *reinterpret_cast<const float2*>(base + (size_t)r * IMG_W + 2 * k);
            *reinterpret_cast<float2*>(Ab + r * PITCH + COFF + 2 * k) = v;
        }
    } else {
        for (int idx = tid; idx < IN * IN; idx += NT) {
            const int r = idx / IN;
            const int c = idx - r * IN;
            int gr = gr0 + r - HALO;
            int gc = gc0 + c - HALO;
            gr = gr < 0 ? -gr : gr;
            gr = gr >= IMG_H ? 2 * IMG_H - 2 - gr : gr;
            gc = gc < 0 ? -gc : gc;
            gc = gc >= IMG_W ? 2 * IMG_W - 2 - gc : gc;
            Ab[r * PITCH + COFF + c] = __ldg(&xb[(size_t)gr * IMG_W + gc]);
        }
    }
    __syncthreads();

    constexpr size_t CHS = (size_t)IMG_H * IMG_W;
    float* outb = out + ((size_t)b * 4) * CHS + (size_t)gr0 * IMG_W + gc0;

    // ---- level 0 (d=1) ----
    hconv_v<1, 2, 90, 11, 0, 24>(Ab, Bb, tid);                 // 264 units
    __syncthreads();
    wconv_fused<1, 2, 90, 1, 23, 2, false>(Bb, Ab, outb, nullptr, tid);  // 176
    __syncthreads();

    // ---- level 1 (d=2) ----
    hconv_v<2, 6, 86, 10, 1, 23>(Ab, Bb, tid);                 // 220 units
    __syncthreads();
    wconv_fused<2, 6, 86, 2, 22, 4, false>(Bb, Ab, outb + CHS, nullptr, tid);  // 320
    __syncthreads();

    // ---- level 2 (d=4) ----
    hconv_v<4, 14, 78, 8, 2, 22>(Ab, Bb, tid);                 // 160 units
    __syncthreads();
    wconv_fused<4, 14, 78, 4, 20, 4, true>(Bb, Ab, outb + 2 * CHS,
                                           outb + 3 * CHS, tid);  // 256
}

extern "C" void kernel_launch(void* const* d_in, const int* in_sizes, int n_in,
                              void* d_out, int out_size) {
    (void)in_sizes; (void)n_in; (void)out_size;
    const float* x = (const float*)d_in[0];
    float* out = (float*)d_out;

    cudaFuncSetAttribute(b3_uwt_kernel,
                         cudaFuncAttributeMaxDynamicSharedMemorySize,
                         SMEM_BYTES);

    dim3 grid(IMG_W / TS, IMG_H / TS, 8);  // 16 x 16 x 8
    b3_uwt_kernel<<<grid, NT, SMEM_BYTES>>>(x, out);
}

// round 4
// speedup vs baseline: 1.3365x; 1.3365x over previous
#include <cuda_runtime.h>

// B3-spline à-trous UWT, J=3, split into 3 single-level kernels.
// (8,1024,1024) fp32 -> (8,4,1024,1024) fp32 = [w1,w2,w3,c3]
//
// Each kernel: vertical 5-tap conv (dilation D) read straight from gmem with
// sliding register windows into a small smem row buffer; one barrier; then
// horizontal conv from smem + re-read of the level input at center (L2-hot)
// to emit w = in - c and c, fully coalesced (lanes along the row).
// Reflect indexing per level reproduces the reference's reflect padding.
// c1 lives in out ch3 (overwritten by c3 later), c2 in a static scratch.

namespace {

constexpr int NT  = 256;
constexpr int IMG = 1024;
constexpr size_t CHS = (size_t)IMG * IMG;

constexpr float W0 = 0.0625f;  // 1/16
constexpr float W1 = 0.25f;    // 1/4
constexpr float W2 = 0.375f;   // 3/8

__device__ float g_scratch[8u * 1024u * 1024u];  // 32MB c2 carrier

__device__ __forceinline__ int refl(int g) {
    g = g < 0 ? -g : g;
    return g >= IMG ? 2 * IMG - 2 - g : g;
}
__device__ __forceinline__ float b3s(float a, float b, float c, float d, float e) {
    return fmaf(c, W2, fmaf(b + d, W1, (a + e) * W0));
}
__device__ __forceinline__ float4 b3v(const float4& a, const float4& b,
                                      const float4& c, const float4& d,
                                      const float4& e) {
    float4 r;
    r.x = b3s(a.x, b.x, c.x, d.x, e.x);
    r.y = b3s(a.y, b.y, c.y, d.y, e.y);
    r.z = b3s(a.z, b.z, c.z, d.z, e.z);
    r.w = b3s(a.w, b.w, c.w, d.w, e.w);
    return r;
}
__device__ __forceinline__ void st4(float* p, float4 v) {
    *reinterpret_cast<float4*>(p) = v;
}
__device__ __forceinline__ float4 ld4(const float* p) {
    return *reinterpret_cast<const float4*>(p);
}

// 16B gmem load; for D==1 the column base is only 8B aligned -> two float2.
template <int D>
__device__ __forceinline__ float4 ldg4(const float* p) {
    if (D == 1) {
        const float2 a = __ldg(reinterpret_cast<const float2*>(p));
        const float2 b = __ldg(reinterpret_cast<const float2*>(p + 2));
        return make_float4(a.x, a.y, b.x, b.y);
    } else {
        return __ldg(reinterpret_cast<const float4*>(p));
    }
}

// One wavelet level, dilation D. NVEC = (64+4D)/4 vec-cols, PB = smem pitch
// (% 8 == 4). SSRC/SDST: source/coeff-dest is the static scratch.
template <int D, int NVEC, int PB, bool SSRC, bool SDST>
__global__ void __launch_bounds__(NT)
lvl_kernel(const float* __restrict__ src, size_t sstride,
           float* __restrict__ wdst,
           float* __restrict__ cdst, size_t cstride) {
    __shared__ float B[64 * PB];

    const int tid = threadIdx.x;
    const int gc0 = blockIdx.x * 64;
    const int gr0 = blockIdx.y * 64;
    const int b   = blockIdx.z;

    const float* s = SSRC ? (g_scratch + (size_t)b * CHS)
                          : (src + (size_t)b * sstride);

    // ---- phase 1: vertical conv (gmem -> smem B), rows 0..63, cols 64+4D ----
    const bool colint = (gc0 >= 2 * D) && (gc0 + 64 + 2 * D <= IMG);
    constexpr int UNITS = NVEC * 8;  // 8 row-segments of 8 output rows
    for (int u = tid; u < UNITS; u += NT) {
        const int vc  = u % NVEC;
        const int rrs = (u / NVEC) * 8;
        const int cb  = gc0 - 2 * D + 4 * vc;
        float* Bp = B + 4 * vc;
        if (colint) {
            const float* cp = s + cb;
#pragma unroll
            for (int p = 0; p < D; ++p) {
                int rr = rrs + p;
                float4 v0 = ldg4<D>(cp + (size_t)refl(gr0 + rr - 2 * D) * IMG);
                float4 v1 = ldg4<D>(cp + (size_t)refl(gr0 + rr - D) * IMG);
                float4 v2 = ldg4<D>(cp + (size_t)refl(gr0 + rr) * IMG);
                float4 v3 = ldg4<D>(cp + (size_t)refl(gr0 + rr + D) * IMG);
#pragma unroll
                for (int i = 0; i < 8 / D; ++i, rr += D) {
                    const float4 v4 =
                        ldg4<D>(cp + (size_t)refl(gr0 + rr + 2 * D) * IMG);
                    st4(Bp + rr * PB, b3v(v0, v1, v2, v3, v4));
                    v0 = v1; v1 = v2; v2 = v3; v3 = v4;
                }
            }
        } else {
            int cc[4];
#pragma unroll
            for (int j = 0; j < 4; ++j) {
                int c = cb + j;
                c = c < 0 ? -c : c;
                cc[j] = c >= IMG ? 2 * IMG - 2 - c : c;
            }
            for (int rr = rrs; rr < rrs + 8; ++rr) {
                const float* r0 = s + (size_t)refl(gr0 + rr - 2 * D) * IMG;
                const float* r1 = s + (size_t)refl(gr0 + rr - D) * IMG;
                const float* r2 = s + (size_t)refl(gr0 + rr) * IMG;
                const float* r3 = s + (size_t)refl(gr0 + rr + D) * IMG;
                const float* r4 = s + (size_t)refl(gr0 + rr + 2 * D) * IMG;
#pragma unroll
                for (int j = 0; j < 4; ++j) {
                    Bp[rr * PB + j] =
                        b3s(__ldg(r0 + cc[j]), __ldg(r1 + cc[j]),
                            __ldg(r2 + cc[j]), __ldg(r3 + cc[j]),
                            __ldg(r4 + cc[j]));
                }
            }
        }
    }
    __syncthreads();

    // ---- phase 2: horizontal conv + diff + coalesced store ----
    const int lane = tid & 31, warp = tid >> 5;
    const int v = lane & 15, sub = lane >> 4;
    float* wd = wdst + (size_t)b * 4 * CHS;
    float* cd = SDST ? (g_scratch + (size_t)b * CHS)
                     : (cdst + (size_t)b * cstride);
#pragma unroll
    for (int i = 0; i < 4; ++i) {
        const int rr = i * 16 + warp * 2 + sub;
        const float* Bp = B + rr * PB + 4 * v;
        float w[4 * (D + 1)];
#pragma unroll
        for (int k = 0; k <= D; ++k) {
            const float4 t = ld4(Bp + 4 * k);
            w[4 * k + 0] = t.x; w[4 * k + 1] = t.y;
            w[4 * k + 2] = t.z; w[4 * k + 3] = t.w;
        }
        float4 o;
        o.x = b3s(w[0], w[D],     w[2 * D],     w[3 * D],     w[4 * D]);
        o.y = b3s(w[1], w[1 + D], w[1 + 2 * D], w[1 + 3 * D], w[1 + 4 * D]);
        o.z = b3s(w[2], w[2 + D], w[2 + 2 * D], w[2 + 3 * D], w[2 + 4 * D]);
        o.w = b3s(w[3], w[3 + D], w[3 + 2 * D], w[3 + 3 * D], w[3 + 4 * D]);

        const size_t go = (size_t)(gr0 + rr) * IMG + gc0 + 4 * v;
        const float4 a = __ldg(reinterpret_cast<const float4*>(s + go));
        st4(wd + go, make_float4(a.x - o.x, a.y - o.y, a.z - o.z, a.w - o.w));
        st4(cd + go, o);
    }
}

}  // namespace

extern "C" void kernel_launch(void* const* d_in, const int* in_sizes, int n_in,
                              void* d_out, int out_size) {
    (void)in_sizes; (void)n_in; (void)out_size;
    const float* x = (const float*)d_in[0];
    float* out = (float*)d_out;

    dim3 grid(IMG / 64, IMG / 64, 8);  // 16 x 16 x 8

    // K1 (d=1): x -> w1 (ch0), c1 -> out ch3
    lvl_kernel<1, 17, 68, false, false><<<grid, NT>>>(
        x, CHS, out, out + 3 * CHS, 4 * CHS);

    // K2 (d=2): c1 (ch3) -> w2 (ch1), c2 -> scratch
    lvl_kernel<2, 18, 76, false, true><<<grid, NT>>>(
        out + 3 * CHS, 4 * CHS, out + CHS, nullptr, 0);

    // K3 (d=4): c2 (scratch) -> w3 (ch2), c3 -> out ch3
    lvl_kernel<4, 20, 84, true, false><<<grid, NT>>>(
        nullptr, 0, out + 2 * CHS, out + 3 * CHS, 4 * CHS);
}